// round 4
// baseline (speedup 1.0000x reference)
#include <cuda_runtime.h>
#include <cstdint>
#include <cstddef>

#define TT 512
#define CC 128
#define LL 80
#define BLANKC 127
#define FEPS 1e-7f
#define FULLM 0xffffffffu
#define DPF 8

// 128 blocks x 128 threads: 4 warps/block -> one warp per SMSP (wid%4 mapping),
// one batch element per warp. States split by parity:
//  e_i = alpha[2i]   (blank, i=0..80): lane l holds e_l, e_{32+l}, e_{64+l}
//  o_i = alpha[2i+1] (label, i=0..79): lane l holds o_l, o_{32+l}, o_{64+l}
// Blank emission is ONE uniform scalar per row (y[t][127]); label gathers are
// 3 LDGs. Gathers AND the full-row softmax-norm float4 stream are ALL
// prefetched DPF=8 rows ahead in registers (ring slot = unroll index), so the
// latency-imposed step time is ~DRAM_lat/8. Linear-domain recursion with
// 8-step lagged rescaling; row log-norms via a 5-stage software-pipelined
// shfl butterfly; float accumulators throughout.
__global__ void __launch_bounds__(128, 1) ctc_kernel(
    const int* __restrict__ lab32,
    const float* __restrict__ ypred,
    float* __restrict__ out)
{
    const int lane = threadIdx.x & 31;
    const int w = threadIdx.x >> 5;
    const int b = blockIdx.x * 4 + w;
    const float* __restrict__ yb = ypred + (size_t)b * (TT * CC);

    // detect label element width (int64 little-endian vs int32)
    int probe = lab32[1] | lab32[3] | lab32[5] | lab32[7]
              | lab32[9] | lab32[11] | lab32[13] | lab32[15];
    const int stride = (probe == 0) ? 2 : 1;
    const int* lb = lab32 + (size_t)b * LL * stride;

    const int i1 = 32 + lane, i2 = 64 + lane;
    const int L0 = lb[lane * stride];
    const int L1 = lb[i1 * stride];
    const bool v2 = (i2 < LL);
    const int L2 = v2 ? lb[i2 * stride] : BLANKC;
    const float al0 = (lane == 0) ? 0.f : ((L0 != lb[(lane - 1) * stride]) ? 1.f : 0.f);
    const float al1 = (L1 != lb[(i1 - 1) * stride]) ? 1.f : 0.f;
    const float al2 = (v2 && (L2 != lb[(i2 - 1) * stride])) ? 1.f : 0.f;

    const float* __restrict__ gB = yb + BLANKC;
    const float* __restrict__ g0 = yb + L0;
    const float* __restrict__ g1 = yb + L1;
    const float* __restrict__ g2 = yb + L2;
    const float* __restrict__ gN = yb + lane * 4;

    // prime DPF-deep pipelines (rows 0..DPF-1): gathers + full-row float4
    float qB[DPF], q0[DPF], q1[DPF], q2[DPF];
    float4 nq[DPF];
#pragma unroll
    for (int r = 0; r < DPF; r++) {
        qB[r] = gB[(size_t)r * CC];
        q0[r] = g0[(size_t)r * CC];
        q1[r] = g1[(size_t)r * CC];
        q2[r] = g2[(size_t)r * CC];
        nq[r] = *(const float4*)(gN + (size_t)r * CC);
    }

    float e0 = 0.f, e1 = 0.f, e2 = 0.f, o0 = 0.f, o1 = 0.f, o2 = 0.f;
    float np0 = 0.f, np1 = 0.f, np2 = 0.f, np3 = 0.f, np4 = 0.f;
    float accN0 = 0.f, accN1 = 0.f, accS = 0.f;
    float rs = 0.f, pend = 0.f, cN = 1.f;
    int t = 0;

#define CTC_STEP(FIRST, U) do {                                                     \
    /* consume slot U (row t), refill with row t+DPF */                             \
    float yB = qB[U] + FEPS;                                                        \
    float y0 = q0[U] + FEPS;                                                        \
    float y1 = q1[U] + FEPS;                                                        \
    float y2 = v2 ? (q2[U] + FEPS) : 0.f;                                           \
    float4 v4 = nq[U];                                                              \
    float loc = (v4.x + v4.y) + (v4.z + v4.w);                                      \
    { int tn = t + DPF;                                                             \
      if (tn < TT) {                                                                \
          qB[U] = gB[(size_t)tn * CC]; q0[U] = g0[(size_t)tn * CC];                 \
          q1[U] = g1[(size_t)tn * CC]; q2[U] = g2[(size_t)tn * CC];                 \
          nq[U] = *(const float4*)(gN + (size_t)tn * CC); } }                       \
    /* norm pipeline: finish row t-5 */                                             \
    if (!(FIRST) || (U) >= 5) {                                                     \
        float fin = np4 + __shfl_xor_sync(FULLM, np4, 1);                           \
        float lg = __logf(fin + (float)CC * FEPS);                                  \
        if (((U) & 1) == 0) accN0 += lg; else accN1 += lg;                          \
    }                                                                               \
    np4 = np3 + __shfl_xor_sync(FULLM, np3, 2);                                     \
    np3 = np2 + __shfl_xor_sync(FULLM, np2, 4);                                     \
    np2 = np1 + __shfl_xor_sync(FULLM, np1, 8);                                     \
    np1 = np0 + __shfl_xor_sync(FULLM, np0, 16);                                    \
    np0 = loc;                                                                      \
    if ((FIRST) && (U) == 0) {                                                      \
        e0 = (lane == 0) ? yB : 0.f;                                                \
        o0 = (lane == 0) ? y0 : 0.f;                                                \
    } else {                                                                        \
        float bb0 = __shfl_sync(FULLM, o0, 31);                                     \
        float bb1 = __shfl_sync(FULLM, o1, 31);                                     \
        float m0 = __shfl_up_sync(FULLM, o0, 1);                                    \
        float m1 = __shfl_up_sync(FULLM, o1, 1);                                    \
        float m2 = __shfl_up_sync(FULLM, o2, 1);                                    \
        if (lane == 0) { m0 = 0.f; m1 = bb0; m2 = bb1; }                            \
        float ne0 = yB * (e0 + m0);                                                 \
        float ne1 = yB * (e1 + m1);                                                 \
        float ne2 = yB * (e2 + m2);                                                 \
        float no0 = y0 * __fmaf_rn(al0, m0, o0 + e0);                               \
        float no1 = y1 * __fmaf_rn(al1, m1, o1 + e1);                               \
        float no2 = y2 * __fmaf_rn(al2, m2, o2 + e2);                               \
        e0 = ne0; e1 = ne1; e2 = ne2; o0 = no0; o1 = no1; o2 = no2;                 \
    }                                                                               \
    /* lagged rescale: one butterfly stage per step, applied at U==7 */             \
    if ((U) == 0)      { rs = ((e0 + e1) + (e2 + o0)) + (o1 + o2); }                \
    else if ((U) == 1) { rs += __shfl_xor_sync(FULLM, rs, 16); }                    \
    else if ((U) == 2) { rs += __shfl_xor_sync(FULLM, rs, 8); }                     \
    else if ((U) == 3) { rs += __shfl_xor_sync(FULLM, rs, 4); }                     \
    else if ((U) == 4) { rs += __shfl_xor_sync(FULLM, rs, 2); }                     \
    else if ((U) == 5) { rs += __shfl_xor_sync(FULLM, rs, 1); }                     \
    else if ((U) == 6) { pend = __logf(rs); cN = __fdividef(1.f, rs); }             \
    else               { e0 *= cN; e1 *= cN; e2 *= cN;                              \
                         o0 *= cN; o1 *= cN; o2 *= cN; accS += pend; }              \
    t++;                                                                            \
} while (0)

    CTC_STEP(1, 0); CTC_STEP(1, 1); CTC_STEP(1, 2); CTC_STEP(1, 3);
    CTC_STEP(1, 4); CTC_STEP(1, 5); CTC_STEP(1, 6); CTC_STEP(1, 7);

#pragma unroll 1
    for (int g = 1; g < TT / 8; g++) {
        CTC_STEP(0, 0); CTC_STEP(0, 1); CTC_STEP(0, 2); CTC_STEP(0, 3);
        CTC_STEP(0, 4); CTC_STEP(0, 5); CTC_STEP(0, 6); CTC_STEP(0, 7);
    }
#undef CTC_STEP

    // drain norm pipeline (rows TT-5 .. TT-1)
#pragma unroll
    for (int d = 0; d < 5; d++) {
        float fin = np4 + __shfl_xor_sync(FULLM, np4, 1);
        float lg = __logf(fin + (float)CC * FEPS);
        if ((d & 1) == 0) accN0 += lg; else accN1 += lg;
        np4 = np3 + __shfl_xor_sync(FULLM, np3, 2);
        np3 = np2 + __shfl_xor_sync(FULLM, np2, 4);
        np2 = np1 + __shfl_xor_sync(FULLM, np1, 8);
        np1 = np0 + __shfl_xor_sync(FULLM, np0, 16);
        np0 = 0.f;
    }

    // tail: states 160 (e_80 = e2@lane16) and 159 (o_79 = o2@lane15)
    float accN = accN0 + accN1;
    float e80 = __shfl_sync(FULLM, e2, 16);
    float o79 = __shfl_sync(FULLM, o2, 15);
    if (lane == 0) {
        out[b] = -(__logf(e80 + o79) + accS - accN);
    }
}

extern "C" void kernel_launch(void* const* d_in, const int* in_sizes, int n_in,
                              void* d_out, int out_size) {
    (void)in_sizes; (void)n_in; (void)out_size;
    const int* labels = (const int*)d_in[0];
    const float* ypred = (const float*)d_in[1];
    float* out = (float*)d_out;
    ctc_kernel<<<128, 128>>>(labels, ypred, out);
}

// round 5
// speedup vs baseline: 1.4270x; 1.4270x over previous
#include <cuda_runtime.h>
#include <cstdint>
#include <cstddef>

#define TT 512
#define CC 128
#define LL 80
#define BLANKC 127
#define FEPS 1e-7f
#define FULLM 0xffffffffu
#define RING 16

__device__ __forceinline__ void cp_async16(void* smem, const void* gmem) {
    unsigned s = (unsigned)__cvta_generic_to_shared(smem);
    asm volatile("cp.async.ca.shared.global [%0], [%1], 16;\n" :: "r"(s), "l"(gmem));
}
__device__ __forceinline__ void cp_commit() {
    asm volatile("cp.async.commit_group;\n" ::: "memory");
}
__device__ __forceinline__ void cp_wait_all() {
    asm volatile("cp.async.wait_group 0;\n" ::: "memory");
}

// 128 blocks x 128 threads: one warp per SMSP, one batch element per warp.
// Streaming: per-warp 16-row smem ring filled by cp.async.ca in 8-row commit
// groups (precise group-counting completion -> no LDG scoreboard aliasing;
// one wait+syncwarp per 8 steps). The .ca also primes L1, so the 4 label
// gathers are short-distance L1-hit LDGs. Row softmax-norm sums read the ring
// via conflict-free LDS.128 (1-step prefetch) and reduce through a 5-stage
// software-pipelined shfl butterfly. States split by parity:
//  e_i = alpha[2i]   (blank, i=0..80): lane l holds e_l, e_{32+l}, e_{64+l}
//  o_i = alpha[2i+1] (label, i=0..79): lane l holds o_l, o_{32+l}, o_{64+l}
// Linear-domain recursion with 8-step lagged rescaling; float accumulators.
__global__ void __launch_bounds__(128, 1) ctc_kernel(
    const int* __restrict__ lab32,
    const float* __restrict__ ypred,
    float* __restrict__ out)
{
    __shared__ __align__(16) float ring[4][RING][CC];   // 32 KB
    const int lane = threadIdx.x & 31;
    const int w = threadIdx.x >> 5;
    const int b = blockIdx.x * 4 + w;
    const float* __restrict__ yb = ypred + (size_t)b * (TT * CC);

    // detect label element width (int64 little-endian vs int32)
    int probe = lab32[1] | lab32[3] | lab32[5] | lab32[7]
              | lab32[9] | lab32[11] | lab32[13] | lab32[15];
    const int stride = (probe == 0) ? 2 : 1;
    const int* lb = lab32 + (size_t)b * LL * stride;

    const int i1 = 32 + lane, i2 = 64 + lane;
    const int L0 = lb[lane * stride];
    const int L1 = lb[i1 * stride];
    const bool v2 = (i2 < LL);
    const int L2 = v2 ? lb[i2 * stride] : BLANKC;
    const float al0 = (lane == 0) ? 0.f : ((L0 != lb[(lane - 1) * stride]) ? 1.f : 0.f);
    const float al1 = (L1 != lb[(i1 - 1) * stride]) ? 1.f : 0.f;
    const float al2 = (v2 && (L2 != lb[(i2 - 1) * stride])) ? 1.f : 0.f;

    const float* __restrict__ gB = yb + BLANKC;
    const float* __restrict__ g0 = yb + L0;
    const float* __restrict__ g1 = yb + L1;
    const float* __restrict__ g2 = yb + L2;

    // prime smem ring with rows 0..7 (one commit group)
#pragma unroll
    for (int r = 0; r < 8; r++)
        cp_async16(&ring[w][r][lane * 4], yb + (size_t)r * CC + lane * 4);
    cp_commit();

    // prime 2-deep gather registers (rows 0,1) — cold, one-time stall
    float qB[2], q0[2], q1[2], q2[2];
#pragma unroll
    for (int r = 0; r < 2; r++) {
        qB[r] = gB[(size_t)r * CC];
        q0[r] = g0[(size_t)r * CC];
        q1[r] = g1[(size_t)r * CC];
        q2[r] = g2[(size_t)r * CC];
    }

    float e0 = 0.f, e1 = 0.f, e2 = 0.f, o0 = 0.f, o1 = 0.f, o2 = 0.f;
    float np0 = 0.f, np1 = 0.f, np2 = 0.f, np3 = 0.f, np4 = 0.f;
    float accN0 = 0.f, accN1 = 0.f, accS = 0.f;
    float rs = 0.f, pend = 0.f, cN = 1.f;
    float4 f4pre = make_float4(0.f, 0.f, 0.f, 0.f);
    int t = 0;

#define CTC_STEP(FIRST, U) do {                                                     \
    float4 v4;                                                                      \
    if ((U) == 0) {                                                                 \
        cp_wait_all();                                                              \
        __syncwarp();                                                               \
        _Pragma("unroll")                                                           \
        for (int j = 0; j < 8; j++) {                                               \
            int tn = t + 8 + j;                                                     \
            if (tn < TT)                                                            \
                cp_async16(&ring[w][tn & (RING - 1)][lane * 4],                     \
                           yb + (size_t)tn * CC + lane * 4);                        \
        }                                                                           \
        cp_commit();                                                                \
        v4 = *(const float4*)&ring[w][t & (RING - 1)][lane * 4];                    \
    } else {                                                                        \
        v4 = f4pre;                                                                 \
    }                                                                               \
    if ((U) < 7)                                                                    \
        f4pre = *(const float4*)&ring[w][(t + 1) & (RING - 1)][lane * 4];           \
    float loc = (v4.x + v4.y) + (v4.z + v4.w);                                      \
    /* gathers: consume 2-deep register slot, refill row t+2 (L1-hot LDG) */        \
    float yB = qB[(U) & 1] + FEPS;                                                  \
    float y0 = q0[(U) & 1] + FEPS;                                                  \
    float y1 = q1[(U) & 1] + FEPS;                                                  \
    float y2 = v2 ? (q2[(U) & 1] + FEPS) : 0.f;                                     \
    { int tn = t + 2;                                                               \
      if (tn < TT) {                                                                \
          qB[(U) & 1] = gB[(size_t)tn * CC]; q0[(U) & 1] = g0[(size_t)tn * CC];     \
          q1[(U) & 1] = g1[(size_t)tn * CC]; q2[(U) & 1] = g2[(size_t)tn * CC]; } } \
    /* norm pipeline: finish row t-5 */                                             \
    if (!(FIRST) || (U) >= 5) {                                                     \
        float fin = np4 + __shfl_xor_sync(FULLM, np4, 1);                           \
        float lg = __logf(fin + (float)CC * FEPS);                                  \
        if (((U) & 1) == 0) accN0 += lg; else accN1 += lg;                          \
    }                                                                               \
    np4 = np3 + __shfl_xor_sync(FULLM, np3, 2);                                     \
    np3 = np2 + __shfl_xor_sync(FULLM, np2, 4);                                     \
    np2 = np1 + __shfl_xor_sync(FULLM, np1, 8);                                     \
    np1 = np0 + __shfl_xor_sync(FULLM, np0, 16);                                    \
    np0 = loc;                                                                      \
    if ((FIRST) && (U) == 0) {                                                      \
        e0 = (lane == 0) ? yB : 0.f;                                                \
        o0 = (lane == 0) ? y0 : 0.f;                                                \
    } else {                                                                        \
        float bb0 = __shfl_sync(FULLM, o0, 31);                                     \
        float bb1 = __shfl_sync(FULLM, o1, 31);                                     \
        float m0 = __shfl_up_sync(FULLM, o0, 1);                                    \
        float m1 = __shfl_up_sync(FULLM, o1, 1);                                    \
        float m2 = __shfl_up_sync(FULLM, o2, 1);                                    \
        if (lane == 0) { m0 = 0.f; m1 = bb0; m2 = bb1; }                            \
        float ne0 = yB * (e0 + m0);                                                 \
        float ne1 = yB * (e1 + m1);                                                 \
        float ne2 = yB * (e2 + m2);                                                 \
        float no0 = y0 * __fmaf_rn(al0, m0, o0 + e0);                               \
        float no1 = y1 * __fmaf_rn(al1, m1, o1 + e1);                               \
        float no2 = y2 * __fmaf_rn(al2, m2, o2 + e2);                               \
        e0 = ne0; e1 = ne1; e2 = ne2; o0 = no0; o1 = no1; o2 = no2;                 \
    }                                                                               \
    /* lagged rescale: one butterfly stage per step, applied at U==7 */             \
    if ((U) == 0)      { rs = ((e0 + e1) + (e2 + o0)) + (o1 + o2); }                \
    else if ((U) == 1) { rs += __shfl_xor_sync(FULLM, rs, 16); }                    \
    else if ((U) == 2) { rs += __shfl_xor_sync(FULLM, rs, 8); }                     \
    else if ((U) == 3) { rs += __shfl_xor_sync(FULLM, rs, 4); }                     \
    else if ((U) == 4) { rs += __shfl_xor_sync(FULLM, rs, 2); }                     \
    else if ((U) == 5) { rs += __shfl_xor_sync(FULLM, rs, 1); }                     \
    else if ((U) == 6) { pend = __logf(rs); cN = __fdividef(1.f, rs); }             \
    else               { e0 *= cN; e1 *= cN; e2 *= cN;                              \
                         o0 *= cN; o1 *= cN; o2 *= cN; accS += pend; }              \
    t++;                                                                            \
} while (0)

    CTC_STEP(1, 0); CTC_STEP(1, 1); CTC_STEP(1, 2); CTC_STEP(1, 3);
    CTC_STEP(1, 4); CTC_STEP(1, 5); CTC_STEP(1, 6); CTC_STEP(1, 7);

#pragma unroll 1
    for (int g = 1; g < TT / 8; g++) {
        CTC_STEP(0, 0); CTC_STEP(0, 1); CTC_STEP(0, 2); CTC_STEP(0, 3);
        CTC_STEP(0, 4); CTC_STEP(0, 5); CTC_STEP(0, 6); CTC_STEP(0, 7);
    }
#undef CTC_STEP

    // drain norm pipeline (rows TT-5 .. TT-1)
#pragma unroll
    for (int d = 0; d < 5; d++) {
        float fin = np4 + __shfl_xor_sync(FULLM, np4, 1);
        float lg = __logf(fin + (float)CC * FEPS);
        if ((d & 1) == 0) accN0 += lg; else accN1 += lg;
        np4 = np3 + __shfl_xor_sync(FULLM, np3, 2);
        np3 = np2 + __shfl_xor_sync(FULLM, np2, 4);
        np2 = np1 + __shfl_xor_sync(FULLM, np1, 8);
        np1 = np0 + __shfl_xor_sync(FULLM, np0, 16);
        np0 = 0.f;
    }

    // tail: states 160 (e_80 = e2@lane16) and 159 (o_79 = o2@lane15)
    float accN = accN0 + accN1;
    float e80 = __shfl_sync(FULLM, e2, 16);
    float o79 = __shfl_sync(FULLM, o2, 15);
    if (lane == 0) {
        out[b] = -(__logf(e80 + o79) + accS - accN);
    }
}

extern "C" void kernel_launch(void* const* d_in, const int* in_sizes, int n_in,
                              void* d_out, int out_size) {
    (void)in_sizes; (void)n_in; (void)out_size;
    const int* labels = (const int*)d_in[0];
    const float* ypred = (const float*)d_in[1];
    float* out = (float*)d_out;
    ctc_kernel<<<128, 128>>>(labels, ypred, out);
}

// round 6
// speedup vs baseline: 2.1733x; 1.5230x over previous
#include <cuda_runtime.h>
#include <cstdint>
#include <cstddef>

#define TT 512
#define CC 128
#define LL 80
#define BLANKC 127
#define FEPS 1e-7f
#define FULLM 0xffffffffu
#define RING 32

__device__ __forceinline__ void cp_async16(void* smem, const void* gmem) {
    unsigned s = (unsigned)__cvta_generic_to_shared(smem);
    asm volatile("cp.async.ca.shared.global [%0], [%1], 16;\n" :: "r"(s), "l"(gmem));
}
__device__ __forceinline__ void cp_commit() {
    asm volatile("cp.async.commit_group;\n" ::: "memory");
}
__device__ __forceinline__ void cp_waitg2() {
    asm volatile("cp.async.wait_group 2;\n" ::: "memory");
}

// 128 blocks x 128 threads: one warp per SMSP, one batch element per warp.
// Streaming: per-warp 32-row smem ring, cp.async in 8-row commit groups with
// wait_group 2 -> THREE groups (12KB/warp, ~6MB chip-wide) in flight at all
// times, pushing DRAM to the LTS cap instead of the 1-group 2.2TB/s
// equilibrium. ALL per-row reads (3 label gathers, blank broadcast, norm
// float4) come from the smem ring via LDS — zero steady-state LDGs, so no
// scoreboard aliasing. Row log-norms via a 5-stage software-pipelined shfl
// butterfly. States split by parity:
//  e_i = alpha[2i]   (blank, i=0..80): lane l holds e_l, e_{32+l}, e_{64+l}
//  o_i = alpha[2i+1] (label, i=0..79): lane l holds o_l, o_{32+l}, o_{64+l}
// Linear-domain recursion with 8-step lagged rescaling; float accumulators.
__global__ void __launch_bounds__(128, 1) ctc_kernel(
    const int* __restrict__ lab32,
    const float* __restrict__ ypred,
    float* __restrict__ out)
{
    extern __shared__ __align__(16) float ring[];   // [4][RING][CC] = 64 KB
    const int lane = threadIdx.x & 31;
    const int w = threadIdx.x >> 5;
    const int b = blockIdx.x * 4 + w;
    float* __restrict__ rw = ring + (size_t)w * RING * CC;
    const float* __restrict__ yb = ypred + (size_t)b * (TT * CC);

    // detect label element width (int64 little-endian vs int32)
    int probe = lab32[1] | lab32[3] | lab32[5] | lab32[7]
              | lab32[9] | lab32[11] | lab32[13] | lab32[15];
    const int stride = (probe == 0) ? 2 : 1;
    const int* lb = lab32 + (size_t)b * LL * stride;

    const int i1 = 32 + lane, i2 = 64 + lane;
    const int L0 = lb[lane * stride];
    const int L1 = lb[i1 * stride];
    const bool v2 = (i2 < LL);
    const int L2 = v2 ? lb[i2 * stride] : BLANKC;
    const float al0 = (lane == 0) ? 0.f : ((L0 != lb[(lane - 1) * stride]) ? 1.f : 0.f);
    const float al1 = (L1 != lb[(i1 - 1) * stride]) ? 1.f : 0.f;
    const float al2 = (v2 && (L2 != lb[(i2 - 1) * stride])) ? 1.f : 0.f;

    // prime 3 groups: rows 0..23
#pragma unroll
    for (int g = 0; g < 3; g++) {
#pragma unroll
        for (int r = 0; r < 8; r++) {
            int row = g * 8 + r;
            cp_async16(rw + row * CC + lane * 4, yb + (size_t)row * CC + lane * 4);
        }
        cp_commit();
    }

    float e0 = 0.f, e1 = 0.f, e2 = 0.f, o0 = 0.f, o1 = 0.f, o2 = 0.f;
    float np0 = 0.f, np1 = 0.f, np2 = 0.f, np3 = 0.f, np4 = 0.f;
    float accN0 = 0.f, accN1 = 0.f, accS = 0.f;
    float rs = 0.f, pend = 0.f, cN = 1.f;
    int t = 0;

#define CTC_STEP(FIRST, U) do {                                                     \
    if ((U) == 0) {                                                                 \
        cp_waitg2();                                                                \
        __syncwarp();                                                               \
        _Pragma("unroll")                                                           \
        for (int j = 0; j < 8; j++) {                                               \
            int tn = t + 24 + j;                                                    \
            if (tn < TT)                                                            \
                cp_async16(rw + (tn & (RING - 1)) * CC + lane * 4,                  \
                           yb + (size_t)tn * CC + lane * 4);                        \
        }                                                                           \
        cp_commit();                                                                \
    }                                                                               \
    const float* rp = rw + (t & (RING - 1)) * CC;                                   \
    float4 v4 = *(const float4*)(rp + lane * 4);                                    \
    float loc = (v4.x + v4.y) + (v4.z + v4.w);                                      \
    float yB = rp[BLANKC] + FEPS;                                                   \
    float y0 = rp[L0] + FEPS;                                                       \
    float y1 = rp[L1] + FEPS;                                                       \
    float y2 = v2 ? (rp[L2] + FEPS) : 0.f;                                          \
    /* norm pipeline: finish row t-5 */                                             \
    if (!(FIRST) || (U) >= 5) {                                                     \
        float fin = np4 + __shfl_xor_sync(FULLM, np4, 1);                           \
        float lg = __logf(fin + (float)CC * FEPS);                                  \
        if (((U) & 1) == 0) accN0 += lg; else accN1 += lg;                          \
    }                                                                               \
    np4 = np3 + __shfl_xor_sync(FULLM, np3, 2);                                     \
    np3 = np2 + __shfl_xor_sync(FULLM, np2, 4);                                     \
    np2 = np1 + __shfl_xor_sync(FULLM, np1, 8);                                     \
    np1 = np0 + __shfl_xor_sync(FULLM, np0, 16);                                    \
    np0 = loc;                                                                      \
    if ((FIRST) && (U) == 0) {                                                      \
        e0 = (lane == 0) ? yB : 0.f;                                                \
        o0 = (lane == 0) ? y0 : 0.f;                                                \
    } else {                                                                        \
        float bb0 = __shfl_sync(FULLM, o0, 31);                                     \
        float bb1 = __shfl_sync(FULLM, o1, 31);                                     \
        float m0 = __shfl_up_sync(FULLM, o0, 1);                                    \
        float m1 = __shfl_up_sync(FULLM, o1, 1);                                    \
        float m2 = __shfl_up_sync(FULLM, o2, 1);                                    \
        if (lane == 0) { m0 = 0.f; m1 = bb0; m2 = bb1; }                            \
        float ne0 = yB * (e0 + m0);                                                 \
        float ne1 = yB * (e1 + m1);                                                 \
        float ne2 = yB * (e2 + m2);                                                 \
        float no0 = y0 * __fmaf_rn(al0, m0, o0 + e0);                               \
        float no1 = y1 * __fmaf_rn(al1, m1, o1 + e1);                               \
        float no2 = y2 * __fmaf_rn(al2, m2, o2 + e2);                               \
        e0 = ne0; e1 = ne1; e2 = ne2; o0 = no0; o1 = no1; o2 = no2;                 \
    }                                                                               \
    /* lagged rescale: one butterfly stage per step, applied at U==7 */             \
    if ((U) == 0)      { rs = ((e0 + e1) + (e2 + o0)) + (o1 + o2); }                \
    else if ((U) == 1) { rs += __shfl_xor_sync(FULLM, rs, 16); }                    \
    else if ((U) == 2) { rs += __shfl_xor_sync(FULLM, rs, 8); }                     \
    else if ((U) == 3) { rs += __shfl_xor_sync(FULLM, rs, 4); }                     \
    else if ((U) == 4) { rs += __shfl_xor_sync(FULLM, rs, 2); }                     \
    else if ((U) == 5) { rs += __shfl_xor_sync(FULLM, rs, 1); }                     \
    else if ((U) == 6) { pend = __logf(rs); cN = __fdividef(1.f, rs); }             \
    else               { e0 *= cN; e1 *= cN; e2 *= cN;                              \
                         o0 *= cN; o1 *= cN; o2 *= cN; accS += pend; }              \
    t++;                                                                            \
} while (0)

    CTC_STEP(1, 0); CTC_STEP(1, 1); CTC_STEP(1, 2); CTC_STEP(1, 3);
    CTC_STEP(1, 4); CTC_STEP(1, 5); CTC_STEP(1, 6); CTC_STEP(1, 7);

#pragma unroll 1
    for (int g = 1; g < TT / 8; g++) {
        CTC_STEP(0, 0); CTC_STEP(0, 1); CTC_STEP(0, 2); CTC_STEP(0, 3);
        CTC_STEP(0, 4); CTC_STEP(0, 5); CTC_STEP(0, 6); CTC_STEP(0, 7);
    }
#undef CTC_STEP

    // drain norm pipeline (rows TT-5 .. TT-1)
#pragma unroll
    for (int d = 0; d < 5; d++) {
        float fin = np4 + __shfl_xor_sync(FULLM, np4, 1);
        float lg = __logf(fin + (float)CC * FEPS);
        if ((d & 1) == 0) accN0 += lg; else accN1 += lg;
        np4 = np3 + __shfl_xor_sync(FULLM, np3, 2);
        np3 = np2 + __shfl_xor_sync(FULLM, np2, 4);
        np2 = np1 + __shfl_xor_sync(FULLM, np1, 8);
        np1 = np0 + __shfl_xor_sync(FULLM, np0, 16);
        np0 = 0.f;
    }

    // tail: states 160 (e_80 = e2@lane16) and 159 (o_79 = o2@lane15)
    float accN = accN0 + accN1;
    float e80 = __shfl_sync(FULLM, e2, 16);
    float o79 = __shfl_sync(FULLM, o2, 15);
    if (lane == 0) {
        out[b] = -(__logf(e80 + o79) + accS - accN);
    }
}

extern "C" void kernel_launch(void* const* d_in, const int* in_sizes, int n_in,
                              void* d_out, int out_size) {
    (void)in_sizes; (void)n_in; (void)out_size;
    const int* labels = (const int*)d_in[0];
    const float* ypred = (const float*)d_in[1];
    float* out = (float*)d_out;
    const int smem = 4 * RING * CC * (int)sizeof(float);   // 64 KB
    cudaFuncSetAttribute(ctc_kernel, cudaFuncAttributeMaxDynamicSharedMemorySize, smem);
    ctc_kernel<<<128, 128, smem>>>(labels, ypred, out);
}

// round 7
// speedup vs baseline: 2.1884x; 1.0069x over previous
#include <cuda_runtime.h>
#include <cstdint>
#include <cstddef>

#define TT 512
#define CC 128
#define LL 80
#define BLANKC 127
#define FEPS 1e-7f
#define FULLM 0xffffffffu
#define RING 48
#define NGRP 5          // commit groups in flight
#define PRIME (8 * NGRP)

__device__ __forceinline__ void cp_async16(void* smem, const void* gmem) {
    unsigned s = (unsigned)__cvta_generic_to_shared(smem);
    asm volatile("cp.async.ca.shared.global [%0], [%1], 16;\n" :: "r"(s), "l"(gmem));
}
__device__ __forceinline__ void cp_commit() {
    asm volatile("cp.async.commit_group;\n" ::: "memory");
}
__device__ __forceinline__ void cp_waitg() {
    asm volatile("cp.async.wait_group %0;\n" :: "n"(NGRP - 1) : "memory");
}

// 128 blocks x 128 threads: one warp per SMSP, one batch element per warp.
// Streaming: per-warp 48-row smem ring, cp.async in 8-row commit groups with
// wait_group 4 -> FIVE groups (20KB/warp, ~10MB chip-wide) in flight,
// pushing DRAM toward the queue-limited ceiling (R5->R6: 1->3 groups gave
// 2.2->3.6 TB/s). ALL per-row reads (3 label gathers, blank broadcast, norm
// float4) come from the smem ring via LDS — zero steady-state LDGs. Row
// log-norms via a 5-stage software-pipelined shfl butterfly. States split by
// parity:
//  e_i = alpha[2i]   (blank, i=0..80): lane l holds e_l, e_{32+l}, e_{64+l}
//  o_i = alpha[2i+1] (label, i=0..79): lane l holds o_l, o_{32+l}, o_{64+l}
// Linear-domain recursion with 8-step lagged rescaling; float accumulators.
__global__ void __launch_bounds__(128, 1) ctc_kernel(
    const int* __restrict__ lab32,
    const float* __restrict__ ypred,
    float* __restrict__ out)
{
    extern __shared__ __align__(16) float ring[];   // [4][RING][CC] = 96 KB
    const int lane = threadIdx.x & 31;
    const int w = threadIdx.x >> 5;
    const int b = blockIdx.x * 4 + w;
    float* __restrict__ rw = ring + (size_t)w * RING * CC;
    const float* __restrict__ yb = ypred + (size_t)b * (TT * CC);

    // detect label element width (int64 little-endian vs int32)
    int probe = lab32[1] | lab32[3] | lab32[5] | lab32[7]
              | lab32[9] | lab32[11] | lab32[13] | lab32[15];
    const int stride = (probe == 0) ? 2 : 1;
    const int* lb = lab32 + (size_t)b * LL * stride;

    const int i1 = 32 + lane, i2 = 64 + lane;
    const int L0 = lb[lane * stride];
    const int L1 = lb[i1 * stride];
    const bool v2 = (i2 < LL);
    const int L2 = v2 ? lb[i2 * stride] : BLANKC;
    const float al0 = (lane == 0) ? 0.f : ((L0 != lb[(lane - 1) * stride]) ? 1.f : 0.f);
    const float al1 = (L1 != lb[(i1 - 1) * stride]) ? 1.f : 0.f;
    const float al2 = (v2 && (L2 != lb[(i2 - 1) * stride])) ? 1.f : 0.f;

    // prime NGRP groups: rows 0..PRIME-1
#pragma unroll
    for (int g = 0; g < NGRP; g++) {
#pragma unroll
        for (int r = 0; r < 8; r++) {
            int row = g * 8 + r;
            cp_async16(rw + row * CC + lane * 4, yb + (size_t)row * CC + lane * 4);
        }
        cp_commit();
    }

    float e0 = 0.f, e1 = 0.f, e2 = 0.f, o0 = 0.f, o1 = 0.f, o2 = 0.f;
    float np0 = 0.f, np1 = 0.f, np2 = 0.f, np3 = 0.f, np4 = 0.f;
    float accN0 = 0.f, accN1 = 0.f, accS = 0.f;
    float rs = 0.f, pend = 0.f, cN = 1.f;
    int t = 0;

#define CTC_STEP(FIRST, U) do {                                                     \
    if ((U) == 0) {                                                                 \
        cp_waitg();                                                                 \
        __syncwarp();                                                               \
        _Pragma("unroll")                                                           \
        for (int j = 0; j < 8; j++) {                                               \
            int tn = t + PRIME + j;                                                 \
            if (tn < TT)                                                            \
                cp_async16(rw + ((tn % RING) * CC) + lane * 4,                      \
                           yb + (size_t)tn * CC + lane * 4);                        \
        }                                                                           \
        cp_commit();                                                                \
    }                                                                               \
    const float* rp = rw + (t % RING) * CC;                                         \
    float4 v4 = *(const float4*)(rp + lane * 4);                                    \
    float loc = (v4.x + v4.y) + (v4.z + v4.w);                                      \
    float yB = rp[BLANKC] + FEPS;                                                   \
    float y0 = rp[L0] + FEPS;                                                       \
    float y1 = rp[L1] + FEPS;                                                       \
    float y2 = v2 ? (rp[L2] + FEPS) : 0.f;                                          \
    /* norm pipeline: finish row t-5 */                                             \
    if (!(FIRST) || (U) >= 5) {                                                     \
        float fin = np4 + __shfl_xor_sync(FULLM, np4, 1);                           \
        float lg = __logf(fin + (float)CC * FEPS);                                  \
        if (((U) & 1) == 0) accN0 += lg; else accN1 += lg;                          \
    }                                                                               \
    np4 = np3 + __shfl_xor_sync(FULLM, np3, 2);                                     \
    np3 = np2 + __shfl_xor_sync(FULLM, np2, 4);                                     \
    np2 = np1 + __shfl_xor_sync(FULLM, np1, 8);                                     \
    np1 = np0 + __shfl_xor_sync(FULLM, np0, 16);                                    \
    np0 = loc;                                                                      \
    if ((FIRST) && (U) == 0) {                                                      \
        e0 = (lane == 0) ? yB : 0.f;                                                \
        o0 = (lane == 0) ? y0 : 0.f;                                                \
    } else {                                                                        \
        float bb0 = __shfl_sync(FULLM, o0, 31);                                     \
        float bb1 = __shfl_sync(FULLM, o1, 31);                                     \
        float m0 = __shfl_up_sync(FULLM, o0, 1);                                    \
        float m1 = __shfl_up_sync(FULLM, o1, 1);                                    \
        float m2 = __shfl_up_sync(FULLM, o2, 1);                                    \
        if (lane == 0) { m0 = 0.f; m1 = bb0; m2 = bb1; }                            \
        float ne0 = yB * (e0 + m0);                                                 \
        float ne1 = yB * (e1 + m1);                                                 \
        float ne2 = yB * (e2 + m2);                                                 \
        float no0 = y0 * __fmaf_rn(al0, m0, o0 + e0);                               \
        float no1 = y1 * __fmaf_rn(al1, m1, o1 + e1);                               \
        float no2 = y2 * __fmaf_rn(al2, m2, o2 + e2);                               \
        e0 = ne0; e1 = ne1; e2 = ne2; o0 = no0; o1 = no1; o2 = no2;                 \
    }                                                                               \
    /* lagged rescale: one butterfly stage per step, applied at U==7 */             \
    if ((U) == 0)      { rs = ((e0 + e1) + (e2 + o0)) + (o1 + o2); }                \
    else if ((U) == 1) { rs += __shfl_xor_sync(FULLM, rs, 16); }                    \
    else if ((U) == 2) { rs += __shfl_xor_sync(FULLM, rs, 8); }                     \
    else if ((U) == 3) { rs += __shfl_xor_sync(FULLM, rs, 4); }                     \
    else if ((U) == 4) { rs += __shfl_xor_sync(FULLM, rs, 2); }                     \
    else if ((U) == 5) { rs += __shfl_xor_sync(FULLM, rs, 1); }                     \
    else if ((U) == 6) { pend = __logf(rs); cN = __fdividef(1.f, rs); }             \
    else               { e0 *= cN; e1 *= cN; e2 *= cN;                              \
                         o0 *= cN; o1 *= cN; o2 *= cN; accS += pend; }              \
    t++;                                                                            \
} while (0)

    CTC_STEP(1, 0); CTC_STEP(1, 1); CTC_STEP(1, 2); CTC_STEP(1, 3);
    CTC_STEP(1, 4); CTC_STEP(1, 5); CTC_STEP(1, 6); CTC_STEP(1, 7);

#pragma unroll 1
    for (int g = 1; g < TT / 8; g++) {
        CTC_STEP(0, 0); CTC_STEP(0, 1); CTC_STEP(0, 2); CTC_STEP(0, 3);
        CTC_STEP(0, 4); CTC_STEP(0, 5); CTC_STEP(0, 6); CTC_STEP(0, 7);
    }
#undef CTC_STEP

    // drain norm pipeline (rows TT-5 .. TT-1)
#pragma unroll
    for (int d = 0; d < 5; d++) {
        float fin = np4 + __shfl_xor_sync(FULLM, np4, 1);
        float lg = __logf(fin + (float)CC * FEPS);
        if ((d & 1) == 0) accN0 += lg; else accN1 += lg;
        np4 = np3 + __shfl_xor_sync(FULLM, np3, 2);
        np3 = np2 + __shfl_xor_sync(FULLM, np2, 4);
        np2 = np1 + __shfl_xor_sync(FULLM, np1, 8);
        np1 = np0 + __shfl_xor_sync(FULLM, np0, 16);
        np0 = 0.f;
    }

    // tail: states 160 (e_80 = e2@lane16) and 159 (o_79 = o2@lane15)
    float accN = accN0 + accN1;
    float e80 = __shfl_sync(FULLM, e2, 16);
    float o79 = __shfl_sync(FULLM, o2, 15);
    if (lane == 0) {
        out[b] = -(__logf(e80 + o79) + accS - accN);
    }
}

extern "C" void kernel_launch(void* const* d_in, const int* in_sizes, int n_in,
                              void* d_out, int out_size) {
    (void)in_sizes; (void)n_in; (void)out_size;
    const int* labels = (const int*)d_in[0];
    const float* ypred = (const float*)d_in[1];
    float* out = (float*)d_out;
    const int smem = 4 * RING * CC * (int)sizeof(float);   // 96 KB
    cudaFuncSetAttribute(ctc_kernel, cudaFuncAttributeMaxDynamicSharedMemorySize, smem);
    ctc_kernel<<<128, 128, smem>>>(labels, ypred, out);
}